// round 3
// baseline (speedup 1.0000x reference)
#include <cuda_runtime.h>
#include <cuda_fp16.h>

// Problem constants
#define T_TOTAL 4096
#define LAYERS  8
#define HIDDEN  1024
#define G4      4096
#define LETTERS 100
#define NCTA    128
#define TPB     256
#define NCELLS  (T_TOTAL * LAYERS)   // 32768

// ---------------------------------------------------------------------------
// Device scratch
// ---------------------------------------------------------------------------
__device__ float g_gin[(size_t)T_TOTAL * LAYERS * G4];        // 512 MB input projections
__device__ __half g_w2[(size_t)LAYERS * NCTA * 8 * 16 * 32 * 8];  // 64 MB repacked fp16 W_hh

// Fused h + sync line: 128B per CTA. h double-buffered by cell parity.
struct __align__(128) HLine {
    float h[2][8];
    int   tag;
    int   pad[15];
};
__device__ HLine g_lines[NCTA];
__device__ __align__(16) float g_c[HIDDEN];

__device__ __forceinline__ int ld_acquire_s32(const int* p) {
    int v;
    asm volatile("ld.acquire.gpu.global.u32 %0, [%1];" : "=r"(v) : "l"(p) : "memory");
    return v;
}
__device__ __forceinline__ void st_release_s32(int* p, int v) {
    asm volatile("st.release.gpu.global.u32 [%0], %1;" :: "l"(p), "r"(v) : "memory");
}
__device__ __forceinline__ float tanh_approx(float x) {
    float y;
    asm("tanh.approx.f32 %0, %1;" : "=f"(y) : "f"(x));
    return y;
}
__device__ __forceinline__ float sigmoid_fast(float x) {
    return 0.5f + 0.5f * tanh_approx(0.5f * x);
}

// ---------------------------------------------------------------------------
// Phase 1a: gin[cell][row] = W_ih@x_t + b_ih + b_hh; also reset state/lines.
// ---------------------------------------------------------------------------
__global__ void precompute_kernel(const float* __restrict__ website,
                                  const float* __restrict__ payload,
                                  const float* __restrict__ W_ih,
                                  const float* __restrict__ b_ih,
                                  const float* __restrict__ b_hh) {
    __shared__ float Xsm[16 * LETTERS];
    const int rt = blockIdx.x;
    const int l  = blockIdx.y;
    const int t0 = blockIdx.z * 16;

    for (int idx = threadIdx.x; idx < 16 * LETTERS; idx += 128) {
        int tt = idx / LETTERS, k = idx % LETTERS;
        int t = t0 + tt;
        Xsm[idx] = (t < 2048) ? website[t * LETTERS + k]
                              : payload[(t - 2048) * LETTERS + k];
    }
    __syncthreads();

    const int row = rt * 128 + threadIdx.x;
    const float* wp = W_ih + ((size_t)l * G4 + row) * LETTERS;

    float acc[16];
#pragma unroll
    for (int tt = 0; tt < 16; tt++) acc[tt] = 0.0f;
    for (int k = 0; k < LETTERS; k++) {
        float w = __ldg(wp + k);
#pragma unroll
        for (int tt = 0; tt < 16; tt++) acc[tt] += w * Xsm[tt * LETTERS + k];
    }
    const float bias = b_ih[l * G4 + row] + b_hh[l * G4 + row];
#pragma unroll
    for (int tt = 0; tt < 16; tt++) {
        size_t idx = (((size_t)(t0 + tt)) * LAYERS + l) * G4 + row;
        g_gin[idx] = acc[tt] + bias;
    }

    if (blockIdx.x == 0 && blockIdx.y == 0 && blockIdx.z == 0 && threadIdx.x < NCTA) {
        HLine* L = &g_lines[threadIdx.x];
#pragma unroll
        for (int q = 0; q < 8; q++) { L->h[0][q] = 0.0f; L->h[1][q] = 0.0f; }
        L->tag = 0;
    }
}

// ---------------------------------------------------------------------------
// Phase 1b: repack W_hh fp32 [l][row][k] -> fp16 compute layout
//   row = g*1024 + bb*8 + j  (g = gate, j = h-index-in-CTA = warp w)
//   k   = s*128 + i*8 + q    (s = lane&7 slice, i = iter, q in 16B chunk)
//   lane = g*8 + s
//   dst halfs: ((((l*128+bb)*8 + w)*16 + i)*32 + lane)*8 + q
// ---------------------------------------------------------------------------
__global__ void repack_whh_kernel(const float* __restrict__ W_hh) {
    size_t idx = (size_t)blockIdx.x * 1024 + threadIdx.x;   // over 8*4096*1024
    int k   = (int)(idx & 1023);
    size_t rowl = idx >> 10;
    int row = (int)(rowl & 4095);
    int l   = (int)(rowl >> 12);
    int g = row >> 10, bb = (row >> 3) & 127, w = row & 7;
    int s = k >> 7, i = (k >> 3) & 15, q = k & 7;
    int lane = g * 8 + s;
    size_t dst = ((((size_t)(l * 128 + bb) * 8 + w) * 16 + i) * 32 + lane) * 8 + q;
    g_w2[dst] = __float2half(W_hh[idx]);
}

// ---------------------------------------------------------------------------
// Phase 2: persistent recurrent kernel. 128 CTAs x 256 threads.
// Warp w computes the 4 gates of h-index bb*8+w; 8 lanes per gate row.
// ---------------------------------------------------------------------------
__global__ void __launch_bounds__(TPB, 1)
lstm_kernel(const float* __restrict__ W_lin,
            const float* __restrict__ b_lin,
            const float* __restrict__ W_out,
            const float* __restrict__ b_out,
            float* __restrict__ out) {
    // padded h: index (s,i,q) -> s*132 + i*8 + q   (conflict-free LDS.128)
    __shared__ __align__(16) float h_sm[8 * 132];
    __shared__ float feat_sm[16];

    const int tid  = threadIdx.x;
    const int bb   = blockIdx.x;
    const int w    = tid >> 5;
    const int lane = tid & 31;
    const int s    = lane & 7;     // k-slice
    // lane's gate g = lane >> 3 (implicit via layout)

    // warp's weight base for layer 0: 16*32*8 = 4096 halfs per (l,bb,w)
    const uint4* __restrict__ wbase0 =
        (const uint4*)(g_w2 + ((size_t)(0 * 128 + bb) * 8 + w) * 4096);
    const size_t layer_stride_u4 = (size_t)128 * 8 * 4096 / 8;   // uint4 per layer

    float c = 0.0f;   // lane 0 of warp w owns c[bb*8+w]
    int p_reg = 0;

    for (int cell = 0; cell < NCELLS; cell++) {
        const int l = cell & 7;
        const int slot = cell & 1;

        // ---- prefetch weights (16 x LDG.128, coalesced) ----
        const uint4* wrow = wbase0 + (size_t)l * layer_stride_u4;
        uint4 wreg[16];
#pragma unroll
        for (int i = 0; i < 16; i++)
            wreg[i] = __ldg(&wrow[i * 32 + lane]);

        // ---- prefetch gin for this warp's 4 gate rows (lanes 0..3) ----
        float gin_reg = 0.0f;
        if (lane < 4)
            gin_reg = __ldcs(&g_gin[(size_t)cell * G4 + lane * HIDDEN + bb * 8 + w]);

        // ---- poll fused h+tag lines, copy h into padded smem ----
        if (tid < NCTA) {
            HLine* L = &g_lines[tid];
            while (ld_acquire_s32(&L->tag) < cell) { }
            float4 a = __ldcg((const float4*)&L->h[slot][0]);
            float4 b = __ldcg((const float4*)&L->h[slot][4]);
            int base = (tid >> 4) * 132 + (tid & 15) * 8;
            *(float4*)&h_sm[base]     = a;
            *(float4*)&h_sm[base + 4] = b;
        }
        __syncthreads();

        // ---- dot product: this lane covers k = s*128 + i*8 + q ----
        float acc = 0.0f;
#pragma unroll
        for (int i = 0; i < 16; i++) {
            const float4 hA = *(const float4*)&h_sm[s * 132 + i * 8];
            const float4 hB = *(const float4*)&h_sm[s * 132 + i * 8 + 4];
            const __half2* hp = (const __half2*)&wreg[i];
            float2 f0 = __half22float2(hp[0]);
            float2 f1 = __half22float2(hp[1]);
            float2 f2 = __half22float2(hp[2]);
            float2 f3 = __half22float2(hp[3]);
            acc += f0.x * hA.x + f0.y * hA.y;
            acc += f1.x * hA.z + f1.y * hA.w;
            acc += f2.x * hB.x + f2.y * hB.y;
            acc += f3.x * hB.z + f3.y * hB.w;
        }
        // reduce across the 8 lanes of each gate row
        acc += __shfl_xor_sync(0xffffffffu, acc, 4);
        acc += __shfl_xor_sync(0xffffffffu, acc, 2);
        acc += __shfl_xor_sync(0xffffffffu, acc, 1);

        // gather the 4 gate sums + gin to lane 0
        float s_i = __shfl_sync(0xffffffffu, acc, 0);
        float s_f = __shfl_sync(0xffffffffu, acc, 8);
        float s_g = __shfl_sync(0xffffffffu, acc, 16);
        float s_o = __shfl_sync(0xffffffffu, acc, 24);
        float g_i = __shfl_sync(0xffffffffu, gin_reg, 0);
        float g_f = __shfl_sync(0xffffffffu, gin_reg, 1);
        float g_g = __shfl_sync(0xffffffffu, gin_reg, 2);
        float g_o = __shfl_sync(0xffffffffu, gin_reg, 3);

        if (lane == 0) {
            float iv = sigmoid_fast(s_i + g_i);
            float fv = sigmoid_fast(s_f + g_f);
            float gv = tanh_approx(s_g + g_g);
            float ov = sigmoid_fast(s_o + g_o);
            c = fv * c + iv * gv;
            float hn = ov * tanh_approx(c);
            g_lines[bb].h[slot ^ 1][w] = hn;   // publish into next-parity slot
        }
        __syncthreads();              // all 8 warps' h stores done
        if (tid == 0) {
            __threadfence();
            st_release_s32(&g_lines[bb].tag, cell + 1);
        }
        p_reg ^= 1;
    }

    // ---- publish final c, then CTA0 computes the output ----
    if (lane == 0) g_c[bb * 8 + w] = c;
    __syncthreads();
    if (tid == 0) {
        __threadfence();
        st_release_s32(&g_lines[bb].tag, NCELLS + 1);
    }

    if (bb == 0) {
        if (tid < NCTA) {
            while (ld_acquire_s32(&g_lines[tid].tag) < NCELLS + 1) { }
        }
        __syncthreads();
        if (tid < 16) {
            const float* wl = W_lin + tid * HIDDEN;
            float a = b_lin[tid];
            for (int k = 0; k < HIDDEN; k++) a += wl[k] * __ldcg(&g_c[k]);
            feat_sm[tid] = a;
        }
        __syncthreads();
        if (tid == 0) {
            float sum = b_out[0];
#pragma unroll
            for (int k = 0; k < 16; k++) sum += W_out[k] * feat_sm[k];
            out[0] = 1.0f / (1.0f + expf(-sum));
        }
    }
}

// ---------------------------------------------------------------------------
// Harness entry. Inputs: 0 website, 1 payload, 2 W_ih, 3 W_hh, 4 b_ih,
// 5 b_hh, 6 W_lin, 7 b_lin, 8 W_out, 9 b_out
// ---------------------------------------------------------------------------
extern "C" void kernel_launch(void* const* d_in, const int* in_sizes, int n_in,
                              void* d_out, int out_size) {
    const float* website = (const float*)d_in[0];
    const float* payload = (const float*)d_in[1];
    const float* W_ih    = (const float*)d_in[2];
    const float* W_hh    = (const float*)d_in[3];
    const float* b_ih    = (const float*)d_in[4];
    const float* b_hh    = (const float*)d_in[5];
    const float* W_lin   = (const float*)d_in[6];
    const float* b_lin   = (const float*)d_in[7];
    const float* W_out   = (const float*)d_in[8];
    const float* b_out   = (const float*)d_in[9];
    float* out = (float*)d_out;

    dim3 grid1(32, 8, 256);
    precompute_kernel<<<grid1, 128>>>(website, payload, W_ih, b_ih, b_hh);
    repack_whh_kernel<<<(LAYERS * G4 * HIDDEN) / 1024, 1024>>>(W_hh);
    lstm_kernel<<<NCTA, TPB>>>(W_lin, b_lin, W_out, b_out, out);
}